// round 6
// baseline (speedup 1.0000x reference)
#include <cuda_runtime.h>
#include <cuda_bf16.h>
#include <cstdint>

#define IN_CH   768
#define OUT_ROW 1536
#define BM      128
#define BN      128
#define BK      64
#define NCHUNK  12          // 768/64
#define NSTAGE  3

#define ROWB    144         // 64 bf16 (128B) + 16B pad -> conflict-free ldsm
#define PLANE   18432       // 128 rows * 144B
#define STGB    36864       // B_hi + B_lo
#define SM_STG(s) (1024 + (s)*STGB)
#define SMEM_TOTAL (1024 + NSTAGE*STGB)   // 111616 B -> 2 CTAs/SM

// Pre-converted weights, gmem layout identical to smem stage layout:
// [mod 3][ntile 4][kchunk 12][plane 2][128 rows][144 B]
__device__ __align__(128) unsigned char g_Bscr[3*4*12*2*PLANE];

static __device__ __forceinline__ uint32_t s2u(const void* p) {
    uint32_t a;
    asm("{ .reg .u64 t; cvta.to.shared.u64 t, %1; cvt.u32.u64 %0, t; }" : "=r"(a) : "l"(p));
    return a;
}
static __device__ __forceinline__ void ldsm4(uint32_t* r, uint32_t addr) {
    asm volatile("ldmatrix.sync.aligned.m8n8.x4.shared.b16 {%0,%1,%2,%3}, [%4];"
                 : "=r"(r[0]), "=r"(r[1]), "=r"(r[2]), "=r"(r[3]) : "r"(addr));
}
static __device__ __forceinline__ void mma16816(float* c, const uint32_t* a, const uint32_t* b) {
    asm volatile("mma.sync.aligned.m16n8k16.row.col.f32.bf16.bf16.f32 "
                 "{%0,%1,%2,%3}, {%4,%5,%6,%7}, {%8,%9}, {%0,%1,%2,%3};"
                 : "+f"(c[0]), "+f"(c[1]), "+f"(c[2]), "+f"(c[3])
                 : "r"(a[0]), "r"(a[1]), "r"(a[2]), "r"(a[3]), "r"(b[0]), "r"(b[1]));
}
static __device__ __forceinline__ void cp16(uint32_t dst, const void* src) {
    asm volatile("cp.async.cg.shared.global [%0], [%1], 16;" :: "r"(dst), "l"(src) : "memory");
}
#define CP_COMMIT asm volatile("cp.async.commit_group;" ::: "memory")
#define CP_WAIT1  asm volatile("cp.async.wait_group 1;" ::: "memory")
#define CP_WAIT0  asm volatile("cp.async.wait_group 0;" ::: "memory")

// precise rn split (weights, runs once)
static __device__ __forceinline__ void split2(float x, float y, uint32_t& hi, uint32_t& lo) {
    __nv_bfloat16 hx = __float2bfloat16_rn(x);
    __nv_bfloat16 hy = __float2bfloat16_rn(y);
    float rx = x - __bfloat162float(hx);
    float ry = y - __bfloat162float(hy);
    __nv_bfloat162 h; h.x = hx; h.y = hy;
    __nv_bfloat162 l; l.x = __float2bfloat16_rn(rx); l.y = __float2bfloat16_rn(ry);
    hi = *reinterpret_cast<uint32_t*>(&h);
    lo = *reinterpret_cast<uint32_t*>(&l);
}
// fast truncation split (activations, per-chunk): hi = PRMT(top halves), lo = rn(x - hi)
static __device__ __forceinline__ void splitA2(float x, float y, uint32_t& hi, uint32_t& lo) {
    uint32_t xu = __float_as_uint(x), yu = __float_as_uint(y);
    hi = __byte_perm(xu, yu, 0x7632);
    float lx = x - __uint_as_float(xu & 0xffff0000u);
    float ly = y - __uint_as_float(yu & 0xffff0000u);
    __nv_bfloat162 l2 = __float22bfloat162_rn(make_float2(lx, ly));
    lo = *reinterpret_cast<uint32_t*>(&l2);
}

// ============ kernel 1: weight conversion ============
__global__ __launch_bounds__(256)
void caps_convw(const float* __restrict__ w_img,
                const float* __restrict__ w_capt,
                const float* __restrict__ w_dct)
{
    int gt  = blockIdx.x * 256 + threadIdx.x;     // [0, 147456)
    int mod = gt / 49152;
    int r   = gt % 49152;
    int n   = r / 96;                             // output col within modality [0,512)
    int k8  = r % 96;                             // 8-float k group
    const float* W = (mod == 0) ? w_img : (mod == 1) ? w_capt : w_dct;
    int wrow = ((n & 7) << 6) | (n >> 3);         // W row for col n = r*8 + c
    const float4* src = (const float4*)(W + (size_t)wrow * IN_CH + k8 * 8);
    float4 p = src[0], q = src[1];
    uint32_t h[4], l[4];
    split2(p.x, p.y, h[0], l[0]); split2(p.z, p.w, h[1], l[1]);
    split2(q.x, q.y, h[2], l[2]); split2(q.z, q.w, h[3], l[3]);
    int ntile = n >> 7, rloc = n & 127;
    int kch = k8 >> 3, kl = k8 & 7;               // 8 k8-groups per 64-k chunk
    size_t base = (size_t)(((mod * 4 + ntile) * 12 + kch) * 2) * PLANE;
    uint32_t off = (uint32_t)(rloc * ROWB + kl * 16);
    *(uint4*)(g_Bscr + base + off)         = make_uint4(h[0], h[1], h[2], h[3]);
    *(uint4*)(g_Bscr + base + PLANE + off) = make_uint4(l[0], l[1], l[2], l[3]);
}

// ============ kernel 2: mma.sync GEMM + bias + squash ============
__global__ __launch_bounds__(256, 2)
void caps_gemm(const float* __restrict__ x_img,
               const float* __restrict__ x_capt,
               const float* __restrict__ x_dct,
               const float* __restrict__ b_img,
               const float* __restrict__ b_capt,
               const float* __restrict__ b_dct,
               float* __restrict__ out)
{
    extern __shared__ __align__(1024) unsigned char smem[];
    const uint32_t sb = s2u(smem);
    float* biasS = (float*)smem;

    const int tid  = threadIdx.x;
    const int lane = tid & 31;
    const int w    = tid >> 5;
    const int wm   = w & 3;            // 4 warps over M (32 rows)
    const int wn   = w >> 2;           // 2 warps over N (64 cols)
    const int b0   = blockIdx.x * BM;
    const int n0   = blockIdx.y * BN;
    const int mod  = blockIdx.z;

    const float* X  = (mod == 0) ? x_img : (mod == 1) ? x_capt : x_dct;
    const float* Bv = (mod == 0) ? b_img : (mod == 1) ? b_capt : b_dct;

    if (tid < BN) {
        int n = n0 + tid;
        biasS[tid] = Bv[((n & 7) << 6) + (n >> 3)];
    }

    // A fragment gmem base: rows b0 + wm*32 + (lane>>2) (+8, +16, +24), k lane-phase (lane&3)*2
    const float* aBase = X + (size_t)(b0 + wm * 32 + (lane >> 2)) * IN_CH + (lane & 3) * 2;

    // B source + cp.async mapping (9 x 16B per thread per stage)
    const unsigned char* bG = g_Bscr + (size_t)((mod * 4 + blockIdx.y) * 12) * 2 * PLANE;

    // B ldsm lane offset within plane
    const uint32_t b_loff = (uint32_t)((wn * 64 + (lane & 7) + ((lane & 16) ? 8 : 0)) * ROWB
                                       + ((lane & 8) ? 16 : 0));

    float acc[2][8][4];
    #pragma unroll
    for (int i = 0; i < 2; ++i)
        #pragma unroll
        for (int j = 0; j < 8; ++j)
            #pragma unroll
            for (int k = 0; k < 4; ++k) acc[i][j][k] = 0.f;

    // prologue: stage chunks 0 and 1
    #pragma unroll
    for (int pc = 0; pc < 2; ++pc) {
        const unsigned char* src = bG + (size_t)pc * STGB;
        uint32_t dst = sb + SM_STG(pc);
        #pragma unroll
        for (int j = 0; j < 9; ++j)
            cp16(dst + tid * 16 + j * 4096, src + tid * 16 + j * 4096);
        CP_COMMIT;
    }

    uint32_t ahf[2][2][4], alf[2][2][4];    // [buf][mt][frag]

    for (int i = 0; i < NCHUNK; ++i) {
        if (i < NCHUNK - 1) { CP_WAIT1; } else { CP_WAIT0; }
        __syncthreads();                     // B(i) visible to all; compute(i-1) done

        if (i + 2 < NCHUNK) {                // refill stage (i+2)%3 (consumed at i-1)
            const unsigned char* src = bG + (size_t)(i + 2) * STGB;
            uint32_t dst = sb + SM_STG((i + 2) % 3);
            #pragma unroll
            for (int j = 0; j < 9; ++j)
                cp16(dst + tid * 16 + j * 4096, src + tid * 16 + j * 4096);
            CP_COMMIT;
        }

        const uint32_t stg = sb + SM_STG(i % 3);
        const float* aC = aBase + i * BK;

        // preload A frags for st=0
        #pragma unroll
        for (int mt = 0; mt < 2; ++mt) {
            const float* p = aC + (size_t)mt * 16 * IN_CH;
            float2 v0 = *(const float2*)p;
            float2 v1 = *(const float2*)(p + 8 * IN_CH);
            float2 v2 = *(const float2*)(p + 8);
            float2 v3 = *(const float2*)(p + 8 * IN_CH + 8);
            splitA2(v0.x, v0.y, ahf[0][mt][0], alf[0][mt][0]);
            splitA2(v1.x, v1.y, ahf[0][mt][1], alf[0][mt][1]);
            splitA2(v2.x, v2.y, ahf[0][mt][2], alf[0][mt][2]);
            splitA2(v3.x, v3.y, ahf[0][mt][3], alf[0][mt][3]);
        }

        #pragma unroll
        for (int st = 0; st < 4; ++st) {
            const int cur = st & 1;
            if (st < 3) {                    // prefetch A frags for st+1
                #pragma unroll
                for (int mt = 0; mt < 2; ++mt) {
                    const float* p = aC + (st + 1) * 16 + (size_t)mt * 16 * IN_CH;
                    float2 v0 = *(const float2*)p;
                    float2 v1 = *(const float2*)(p + 8 * IN_CH);
                    float2 v2 = *(const float2*)(p + 8);
                    float2 v3 = *(const float2*)(p + 8 * IN_CH + 8);
                    splitA2(v0.x, v0.y, ahf[cur^1][mt][0], alf[cur^1][mt][0]);
                    splitA2(v1.x, v1.y, ahf[cur^1][mt][1], alf[cur^1][mt][1]);
                    splitA2(v2.x, v2.y, ahf[cur^1][mt][2], alf[cur^1][mt][2]);
                    splitA2(v3.x, v3.y, ahf[cur^1][mt][3], alf[cur^1][mt][3]);
                }
            }
            #pragma unroll
            for (int g = 0; g < 4; ++g) {
                uint32_t bh[4], bl[4];
                uint32_t base = stg + b_loff + g * (16 * ROWB) + st * 32;
                ldsm4(bh, base);             // hi plane
                ldsm4(bl, base + PLANE);     // lo plane
                #pragma unroll
                for (int half = 0; half < 2; ++half) {
                    const uint32_t* BH = &bh[half * 2];
                    const uint32_t* BL = &bl[half * 2];
                    #pragma unroll
                    for (int mt = 0; mt < 2; ++mt) {
                        float* c = acc[mt][2 * g + half];
                        mma16816(c, ahf[cur][mt], BH);   // hi*hi
                        mma16816(c, ahf[cur][mt], BL);   // hi*lo
                        mma16816(c, alf[cur][mt], BH);   // lo*hi
                    }
                }
            }
        }
    }

    // ---- epilogue: bias + squash (8-col group == one n8 tile) ----
    const int t4 = lane & 3, g8 = lane >> 2;
    #pragma unroll
    for (int mt = 0; mt < 2; ++mt) {
        const int row0 = b0 + wm * 32 + mt * 16 + g8;
        #pragma unroll
        for (int nt = 0; nt < 8; ++nt) {
            float* c = acc[mt][nt];
            const int cl = wn * 64 + nt * 8 + 2 * t4;
            const float bx = biasS[cl], by = biasS[cl + 1];
            float u0 = c[0] + bx, u1 = c[1] + by;
            float u2 = c[2] + bx, u3 = c[3] + by;
            float s0 = u0 * u0 + u1 * u1;
            float s1 = u2 * u2 + u3 * u3;
            s0 += __shfl_xor_sync(0xffffffffu, s0, 1);
            s0 += __shfl_xor_sync(0xffffffffu, s0, 2);
            s1 += __shfl_xor_sync(0xffffffffu, s1, 1);
            s1 += __shfl_xor_sync(0xffffffffu, s1, 2);
            float sc0 = s0 / ((1.0f + s0) * sqrtf(s0 + 1e-7f));
            float sc1 = s1 / ((1.0f + s1) * sqrtf(s1 + 1e-7f));
            float* p0 = out + (size_t)row0 * OUT_ROW + mod * 512 + n0 + cl;
            float* p1 = p0 + 8 * OUT_ROW;
            *(float2*)p0 = make_float2(u0 * sc0, u1 * sc0);
            *(float2*)p1 = make_float2(u2 * sc1, u3 * sc1);
        }
    }
}

extern "C" void kernel_launch(void* const* d_in, const int* in_sizes, int n_in,
                              void* d_out, int out_size)
{
    const float* x_img  = (const float*)d_in[0];
    const float* x_capt = (const float*)d_in[1];
    const float* x_dct  = (const float*)d_in[2];
    const float* w_img  = (const float*)d_in[3];
    const float* b_img  = (const float*)d_in[4];
    const float* w_capt = (const float*)d_in[5];
    const float* b_capt = (const float*)d_in[6];
    const float* w_dct  = (const float*)d_in[7];
    const float* b_dct  = (const float*)d_in[8];
    float* out = (float*)d_out;

    cudaFuncSetAttribute(caps_gemm, cudaFuncAttributeMaxDynamicSharedMemorySize, SMEM_TOTAL);

    caps_convw<<<576, 256>>>(w_img, w_capt, w_dct);

    dim3 grid(16384 / BM, 512 / BN, 3);   // (128, 4, 3)
    caps_gemm<<<grid, 256, SMEM_TOTAL>>>(x_img, x_capt, x_dct,
                                         b_img, b_capt, b_dct, out);
}

// round 7
// speedup vs baseline: 1.3664x; 1.3664x over previous
#include <cuda_runtime.h>
#include <cuda_fp16.h>
#include <cstdint>

#define IN_CH   768
#define OUT_ROW 1536
#define BM      128
#define BN      128
#define BK      32
#define NCHUNK  24          // 768/32

// smem: [0,1024) bias | 3 stages of 24576B: A_hi 8K | A_lo 8K | B 8K
#define STGB     24576
#define SM_STG(s) (1024 + (s)*STGB)
#define OFF_ALO  8192
#define OFF_B    16384
#define SMEM_TOTAL (1024 + 3*STGB)   // 74752 -> 2 CTAs/SM

// Pre-converted fp16 weights, swizzled 64B rows, layout == smem stage B block:
// [mod 3][ntile 4][kchunk 24][128 rows][64 B]
__device__ __align__(128) unsigned char g_Bscr[3*4*24*8192];

static __device__ __forceinline__ uint32_t s2u(const void* p) {
    uint32_t a;
    asm("{ .reg .u64 t; cvta.to.shared.u64 t, %1; cvt.u32.u64 %0, t; }" : "=r"(a) : "l"(p));
    return a;
}
static __device__ __forceinline__ void ldsm4(uint32_t* r, uint32_t addr) {
    asm volatile("ldmatrix.sync.aligned.m8n8.x4.shared.b16 {%0,%1,%2,%3}, [%4];"
                 : "=r"(r[0]), "=r"(r[1]), "=r"(r[2]), "=r"(r[3]) : "r"(addr));
}
static __device__ __forceinline__ void mma16816(float* c, const uint32_t* a, const uint32_t* b) {
    asm volatile("mma.sync.aligned.m16n8k16.row.col.f32.f16.f16.f32 "
                 "{%0,%1,%2,%3}, {%4,%5,%6,%7}, {%8,%9}, {%0,%1,%2,%3};"
                 : "+f"(c[0]), "+f"(c[1]), "+f"(c[2]), "+f"(c[3])
                 : "r"(a[0]), "r"(a[1]), "r"(a[2]), "r"(a[3]), "r"(b[0]), "r"(b[1]));
}
static __device__ __forceinline__ void cp16(uint32_t dst, const void* src) {
    asm volatile("cp.async.cg.shared.global [%0], [%1], 16;" :: "r"(dst), "l"(src) : "memory");
}
#define CP_COMMIT asm volatile("cp.async.commit_group;" ::: "memory")
#define CP_WAIT1  asm volatile("cp.async.wait_group 1;" ::: "memory")
#define CP_WAIT0  asm volatile("cp.async.wait_group 0;" ::: "memory")

// fp32 -> packed fp16 (hi) + fp16 (lo = rn(x - hi)) for two values
static __device__ __forceinline__ void splitH2(float x, float y, uint32_t& hi, uint32_t& lo) {
    __half2 h = __float22half2_rn(make_float2(x, y));
    float rx = x - __half2float(__low2half(h));
    float ry = y - __half2float(__high2half(h));
    __half2 l = __float22half2_rn(make_float2(rx, ry));
    hi = *reinterpret_cast<uint32_t*>(&h);
    lo = *reinterpret_cast<uint32_t*>(&l);
}

// ============ kernel 1: weight conversion (fp16 rn, swizzled) ============
__global__ __launch_bounds__(256)
void caps_convw(const float* __restrict__ w_img,
                const float* __restrict__ w_capt,
                const float* __restrict__ w_dct)
{
    int gt  = blockIdx.x * 256 + threadIdx.x;     // [0, 147456)
    int mod = gt / 49152;
    int r   = gt % 49152;
    int n   = r / 96;                             // output col within modality [0,512)
    int k8  = r % 96;                             // 8-float k group
    const float* W = (mod == 0) ? w_img : (mod == 1) ? w_capt : w_dct;
    int wrow = ((n & 7) << 6) | (n >> 3);         // W row for col n = r*8 + c
    const float4* src = (const float4*)(W + (size_t)wrow * IN_CH + k8 * 8);
    float4 p = src[0], q = src[1];
    __half2 h0 = __float22half2_rn(make_float2(p.x, p.y));
    __half2 h1 = __float22half2_rn(make_float2(p.z, p.w));
    __half2 h2 = __float22half2_rn(make_float2(q.x, q.y));
    __half2 h3 = __float22half2_rn(make_float2(q.z, q.w));
    int ntile = n >> 7, rloc = n & 127;
    int kch = k8 >> 2, c = k8 & 3;                // 4 cells (16B) per 32-k chunk
    uint32_t off = (uint32_t)(rloc * 64 + ((((rloc >> 1) & 3) ^ c) * 16));
    unsigned char* dst = g_Bscr + (size_t)((mod * 4 + ntile) * 24 + kch) * 8192 + off;
    *(uint4*)dst = make_uint4(*(uint32_t*)&h0, *(uint32_t*)&h1, *(uint32_t*)&h2, *(uint32_t*)&h3);
}

// ============ kernel 2: mma.sync GEMM + bias + squash ============
__global__ __launch_bounds__(256, 2)
void caps_gemm(const float* __restrict__ x_img,
               const float* __restrict__ x_capt,
               const float* __restrict__ x_dct,
               const float* __restrict__ b_img,
               const float* __restrict__ b_capt,
               const float* __restrict__ b_dct,
               float* __restrict__ out)
{
    extern __shared__ __align__(1024) unsigned char smem[];
    const uint32_t sb = s2u(smem);
    float* biasS = (float*)smem;

    const int tid  = threadIdx.x;
    const int lane = tid & 31;
    const int w    = tid >> 5;
    const int wm   = w & 3;            // 4 warps over M (32 rows)
    const int wn   = w >> 2;           // 2 warps over N (64 cols)
    const int b0   = blockIdx.x * BM;
    const int n0   = blockIdx.y * BN;
    const int mod  = blockIdx.z;

    const float* X  = (mod == 0) ? x_img : (mod == 1) ? x_capt : x_dct;
    const float* Bv = (mod == 0) ? b_img : (mod == 1) ? b_capt : b_dct;

    if (tid < BN) {
        int n = n0 + tid;
        biasS[tid] = Bv[((n & 7) << 6) + (n >> 3)];
    }

    // A producer: row ar = tid>>1, k-half ah = tid&1 (16 floats)
    const int ar = tid >> 1, ah = tid & 1;
    const float* aG = X + (size_t)(b0 + ar) * IN_CH + ah * 16;
    const uint32_t aw_off = (uint32_t)(ar * 64 + ((((ar >> 1) & 3) ^ (2 * ah)) * 16)); // cell 2*ah

    // B source (layout == smem B block); 2 cp16 per thread per stage
    const unsigned char* bG = g_Bscr + (size_t)((mod * 4 + blockIdx.y) * 24) * 8192;

    // ldsm consumer bases (swizzled)
    const int aRow = wm * 32 + (lane & 15);
    const int lcA  = (lane >> 4) & 1;
    const uint32_t a_base = (uint32_t)(aRow * 64 + ((((aRow >> 1) & 3) ^ lcA) * 16));
    const int bRow = wn * 64 + (lane & 7) + ((lane & 16) ? 8 : 0);
    const int lcB  = (lane >> 3) & 1;
    const uint32_t b_base = (uint32_t)(bRow * 64 + ((((bRow >> 1) & 3) ^ lcB) * 16));

    float acc[2][8][4];
    #pragma unroll
    for (int i = 0; i < 2; ++i)
        #pragma unroll
        for (int j = 0; j < 8; ++j)
            #pragma unroll
            for (int k = 0; k < 4; ++k) acc[i][j][k] = 0.f;

    // ---- producer helper (A split + STS, B cp.async) inlined twice below ----
    // prologue: fill stages 0 and 1 (chunks 0,1)
    #pragma unroll
    for (int pc = 0; pc < 2; ++pc) {
        const float4* ap = (const float4*)(aG + pc * BK);
        float4 v0 = ap[0], v1 = ap[1], v2 = ap[2], v3 = ap[3];
        uint32_t h[8], l[8];
        splitH2(v0.x, v0.y, h[0], l[0]); splitH2(v0.z, v0.w, h[1], l[1]);
        splitH2(v1.x, v1.y, h[2], l[2]); splitH2(v1.z, v1.w, h[3], l[3]);
        splitH2(v2.x, v2.y, h[4], l[4]); splitH2(v2.z, v2.w, h[5], l[5]);
        splitH2(v3.x, v3.y, h[6], l[6]); splitH2(v3.z, v3.w, h[7], l[7]);
        unsigned char* st0 = smem + SM_STG(pc);
        *(uint4*)(st0 + aw_off)                    = make_uint4(h[0], h[1], h[2], h[3]);
        *(uint4*)(st0 + (aw_off ^ 16))             = make_uint4(h[4], h[5], h[6], h[7]);
        *(uint4*)(st0 + OFF_ALO + aw_off)          = make_uint4(l[0], l[1], l[2], l[3]);
        *(uint4*)(st0 + OFF_ALO + (aw_off ^ 16))   = make_uint4(l[4], l[5], l[6], l[7]);
        const unsigned char* src = bG + (size_t)pc * 8192;
        uint32_t dst = sb + SM_STG(pc) + OFF_B;
        cp16(dst + tid * 16,        src + tid * 16);
        cp16(dst + tid * 16 + 4096, src + tid * 16 + 4096);
        CP_COMMIT;
    }
    CP_WAIT1;
    __syncthreads();

    for (int i = 0; i < NCHUNK; ++i) {
        // ---- fill stage (i+2)%3 with chunk i+2 ----
        if (i + 2 < NCHUNK) {
            const int s2 = (i + 2) % 3;
            const float4* ap = (const float4*)(aG + (i + 2) * BK);
            float4 v0 = ap[0], v1 = ap[1], v2 = ap[2], v3 = ap[3];
            uint32_t h[8], l[8];
            splitH2(v0.x, v0.y, h[0], l[0]); splitH2(v0.z, v0.w, h[1], l[1]);
            splitH2(v1.x, v1.y, h[2], l[2]); splitH2(v1.z, v1.w, h[3], l[3]);
            splitH2(v2.x, v2.y, h[4], l[4]); splitH2(v2.z, v2.w, h[5], l[5]);
            splitH2(v3.x, v3.y, h[6], l[6]); splitH2(v3.z, v3.w, h[7], l[7]);
            unsigned char* st2 = smem + SM_STG(s2);
            *(uint4*)(st2 + aw_off)                  = make_uint4(h[0], h[1], h[2], h[3]);
            *(uint4*)(st2 + (aw_off ^ 16))           = make_uint4(h[4], h[5], h[6], h[7]);
            *(uint4*)(st2 + OFF_ALO + aw_off)        = make_uint4(l[0], l[1], l[2], l[3]);
            *(uint4*)(st2 + OFF_ALO + (aw_off ^ 16)) = make_uint4(l[4], l[5], l[6], l[7]);
            const unsigned char* src = bG + (size_t)(i + 2) * 8192;
            uint32_t dst = sb + SM_STG(s2) + OFF_B;
            cp16(dst + tid * 16,        src + tid * 16);
            cp16(dst + tid * 16 + 4096, src + tid * 16 + 4096);
            CP_COMMIT;
        }

        // ---- compute chunk i from stage i%3 ----
        const uint32_t stg = sb + SM_STG(i % 3);
        #pragma unroll
        for (int st = 0; st < 2; ++st) {
            const uint32_t sx = (uint32_t)(st << 5);
            uint32_t ahf[2][4], alf[2][4];
            #pragma unroll
            for (int mt = 0; mt < 2; ++mt) {
                uint32_t base = (stg + a_base + mt * 1024) ^ sx;
                ldsm4(ahf[mt], base);
                ldsm4(alf[mt], base + OFF_ALO);
            }
            #pragma unroll
            for (int g = 0; g < 4; ++g) {
                uint32_t bh[4];
                ldsm4(bh, (stg + OFF_B + b_base + g * 1024) ^ sx);
                #pragma unroll
                for (int half = 0; half < 2; ++half) {
                    const uint32_t* BH = &bh[half * 2];
                    #pragma unroll
                    for (int mt = 0; mt < 2; ++mt) {
                        float* c = acc[mt][2 * g + half];
                        mma16816(c, ahf[mt], BH);   // ah*bh
                        mma16816(c, alf[mt], BH);   // al*bh
                    }
                }
            }
        }

        if (i < NCHUNK - 2)      { CP_WAIT1; }
        else if (i == NCHUNK - 2){ CP_WAIT0; }
        if (i < NCHUNK - 1) __syncthreads();
    }

    // ---- epilogue: bias + squash (8-col group == one n8 tile) ----
    const int t4 = lane & 3, g8 = lane >> 2;
    #pragma unroll
    for (int mt = 0; mt < 2; ++mt) {
        const int row0 = b0 + wm * 32 + mt * 16 + g8;
        #pragma unroll
        for (int nt = 0; nt < 8; ++nt) {
            float* c = acc[mt][nt];
            const int cl = wn * 64 + nt * 8 + 2 * t4;
            const float bx = biasS[cl], by = biasS[cl + 1];
            float u0 = c[0] + bx, u1 = c[1] + by;
            float u2 = c[2] + bx, u3 = c[3] + by;
            float s0 = u0 * u0 + u1 * u1;
            float s1 = u2 * u2 + u3 * u3;
            s0 += __shfl_xor_sync(0xffffffffu, s0, 1);
            s0 += __shfl_xor_sync(0xffffffffu, s0, 2);
            s1 += __shfl_xor_sync(0xffffffffu, s1, 1);
            s1 += __shfl_xor_sync(0xffffffffu, s1, 2);
            float sc0 = s0 / ((1.0f + s0) * sqrtf(s0 + 1e-7f));
            float sc1 = s1 / ((1.0f + s1) * sqrtf(s1 + 1e-7f));
            float* p0 = out + (size_t)row0 * OUT_ROW + mod * 512 + n0 + cl;
            float* p1 = p0 + 8 * OUT_ROW;
            *(float2*)p0 = make_float2(u0 * sc0, u1 * sc0);
            *(float2*)p1 = make_float2(u2 * sc1, u3 * sc1);
        }
    }
}

extern "C" void kernel_launch(void* const* d_in, const int* in_sizes, int n_in,
                              void* d_out, int out_size)
{
    const float* x_img  = (const float*)d_in[0];
    const float* x_capt = (const float*)d_in[1];
    const float* x_dct  = (const float*)d_in[2];
    const float* w_img  = (const float*)d_in[3];
    const float* b_img  = (const float*)d_in[4];
    const float* w_capt = (const float*)d_in[5];
    const float* b_capt = (const float*)d_in[6];
    const float* w_dct  = (const float*)d_in[7];
    const float* b_dct  = (const float*)d_in[8];
    float* out = (float*)d_out;

    cudaFuncSetAttribute(caps_gemm, cudaFuncAttributeMaxDynamicSharedMemorySize, SMEM_TOTAL);

    caps_convw<<<576, 256>>>(w_img, w_capt, w_dct);

    dim3 grid(16384 / BM, 512 / BN, 3);   // (128, 4, 3)
    caps_gemm<<<grid, 256, SMEM_TOTAL>>>(x_img, x_capt, x_dct,
                                         b_img, b_capt, b_dct, out);
}

// round 8
// speedup vs baseline: 1.4109x; 1.0325x over previous
#include <cuda_runtime.h>
#include <cuda_fp16.h>
#include <cstdint>

#define IN_CH   768
#define OUT_ROW 1536
#define BM      128
#define BN      128
#define BK      64
#define NCHUNK  12          // 768/64

// smem: [0,1024) bias | 3 stages of 32768B: A 16K | B 16K
#define STGB     32768
#define SM_STG(s) (1024 + (s)*STGB)
#define OFF_B    16384
#define SMEM_TOTAL (1024 + 3*STGB)   // 99328 -> 2 CTAs/SM

#define SWZ(o) ((o) ^ (((o) >> 3) & 0x70))

// Pre-converted fp16 weights, SW128-swizzled 128B rows, layout == smem B block:
// [mod 3][ntile 4][kchunk 12][128 rows][128 B]
__device__ __align__(128) unsigned char g_Bscr[3*4*12*16384];

static __device__ __forceinline__ uint32_t s2u(const void* p) {
    uint32_t a;
    asm("{ .reg .u64 t; cvta.to.shared.u64 t, %1; cvt.u32.u64 %0, t; }" : "=r"(a) : "l"(p));
    return a;
}
static __device__ __forceinline__ void ldsm4(uint32_t* r, uint32_t addr) {
    asm volatile("ldmatrix.sync.aligned.m8n8.x4.shared.b16 {%0,%1,%2,%3}, [%4];"
                 : "=r"(r[0]), "=r"(r[1]), "=r"(r[2]), "=r"(r[3]) : "r"(addr));
}
static __device__ __forceinline__ void mma16816(float* c, const uint32_t* a, const uint32_t* b) {
    asm volatile("mma.sync.aligned.m16n8k16.row.col.f32.f16.f16.f32 "
                 "{%0,%1,%2,%3}, {%4,%5,%6,%7}, {%8,%9}, {%0,%1,%2,%3};"
                 : "+f"(c[0]), "+f"(c[1]), "+f"(c[2]), "+f"(c[3])
                 : "r"(a[0]), "r"(a[1]), "r"(a[2]), "r"(a[3]), "r"(b[0]), "r"(b[1]));
}
static __device__ __forceinline__ void cp16(uint32_t dst, const void* src) {
    asm volatile("cp.async.cg.shared.global [%0], [%1], 16;" :: "r"(dst), "l"(src) : "memory");
}
#define CP_COMMIT asm volatile("cp.async.commit_group;" ::: "memory")
#define CP_WAIT1  asm volatile("cp.async.wait_group 1;" ::: "memory")
#define CP_WAIT0  asm volatile("cp.async.wait_group 0;" ::: "memory")

// ============ kernel 1: weight conversion (fp16 rn, swizzled) ============
__global__ __launch_bounds__(256)
void caps_convw(const float* __restrict__ w_img,
                const float* __restrict__ w_capt,
                const float* __restrict__ w_dct)
{
    int gt  = blockIdx.x * 256 + threadIdx.x;     // [0, 147456)
    int mod = gt / 49152;
    int r   = gt % 49152;
    int n   = r / 96;                             // output col within modality [0,512)
    int k8  = r % 96;                             // 8-float k group
    const float* W = (mod == 0) ? w_img : (mod == 1) ? w_capt : w_dct;
    int wrow = ((n & 7) << 6) | (n >> 3);         // W row for col n = r*8 + c
    const float4* src = (const float4*)(W + (size_t)wrow * IN_CH + k8 * 8);
    float4 p = src[0], q = src[1];
    __half2 h0 = __float22half2_rn(make_float2(p.x, p.y));
    __half2 h1 = __float22half2_rn(make_float2(p.z, p.w));
    __half2 h2 = __float22half2_rn(make_float2(q.x, q.y));
    __half2 h3 = __float22half2_rn(make_float2(q.z, q.w));
    int ntile = n >> 7, rloc = n & 127;
    int kch = k8 >> 3, cell = k8 & 7;             // 8 cells (16B) per 64-k chunk
    uint32_t off = SWZ((uint32_t)(rloc * 128 + cell * 16));
    unsigned char* dst = g_Bscr + (size_t)((mod * 4 + ntile) * 12 + kch) * 16384 + off;
    *(uint4*)dst = make_uint4(*(uint32_t*)&h0, *(uint32_t*)&h1, *(uint32_t*)&h2, *(uint32_t*)&h3);
}

// ============ kernel 2: fp16 mma.sync GEMM + bias + squash ============
__global__ __launch_bounds__(256, 2)
void caps_gemm(const float* __restrict__ x_img,
               const float* __restrict__ x_capt,
               const float* __restrict__ x_dct,
               const float* __restrict__ b_img,
               const float* __restrict__ b_capt,
               const float* __restrict__ b_dct,
               float* __restrict__ out)
{
    extern __shared__ __align__(1024) unsigned char smem[];
    const uint32_t sb = s2u(smem);
    float* biasS = (float*)smem;

    const int tid  = threadIdx.x;
    const int lane = tid & 31;
    const int w    = tid >> 5;
    const int wm   = w & 3;            // 4 warps over M (32 rows)
    const int wn   = w >> 2;           // 2 warps over N (64 cols)
    const int b0   = blockIdx.x * BM;
    const int n0   = blockIdx.y * BN;
    const int mod  = blockIdx.z;

    const float* X  = (mod == 0) ? x_img : (mod == 1) ? x_capt : x_dct;
    const float* Bv = (mod == 0) ? b_img : (mod == 1) ? b_capt : b_dct;

    if (tid < BN) {
        int n = n0 + tid;
        biasS[tid] = Bv[((n & 7) << 6) + (n >> 3)];
    }

    // A producer: row rA = tid>>1, k-half hA = tid&1 (32 floats -> 64B fp16)
    const int rA = tid >> 1, hA = tid & 1;
    const float* aG = X + (size_t)(b0 + rA) * IN_CH + hA * 32;
    const uint32_t aRowBase = (uint32_t)(rA * 128);
    const uint32_t aXor = (uint32_t)((rA & 7) << 4);
    const uint32_t aCell0 = (uint32_t)(hA * 64);

    // B source (gmem layout == smem B block)
    const unsigned char* bG = g_Bscr + (size_t)((mod * 4 + blockIdx.y) * 12) * 16384;

    // ldsm consumer bases
    const int aRowL = wm * 32 + (lane & 15);
    const uint32_t aL_base = (uint32_t)(aRowL * 128);
    const uint32_t aL_cell = (uint32_t)(((lane >> 4) & 1) * 16);
    const int bRowL = wn * 64 + (lane & 7) + ((lane & 16) ? 8 : 0);
    const uint32_t bL_base = (uint32_t)(bRowL * 128);
    const uint32_t bL_cell = (uint32_t)((lane & 8) ? 16 : 0);
    const uint32_t bXor = (uint32_t)((lane & 7) << 4);

    float acc[2][8][4];
    #pragma unroll
    for (int i = 0; i < 2; ++i)
        #pragma unroll
        for (int j = 0; j < 8; ++j)
            #pragma unroll
            for (int k = 0; k < 4; ++k) acc[i][j][k] = 0.f;

    // ---- prologue: fill stages 0,1 with chunks 0,1 ----
    #pragma unroll
    for (int pc = 0; pc < 2; ++pc) {
        const float4* ap = (const float4*)(aG + pc * BK);
        uint32_t h[16];
        #pragma unroll
        for (int j = 0; j < 8; ++j) {
            float4 v = ap[j];
            __half2 a = __float22half2_rn(make_float2(v.x, v.y));
            __half2 b = __float22half2_rn(make_float2(v.z, v.w));
            h[2*j]   = *(uint32_t*)&a;
            h[2*j+1] = *(uint32_t*)&b;
        }
        unsigned char* st0 = smem + SM_STG(pc);
        #pragma unroll
        for (int j = 0; j < 4; ++j)
            *(uint4*)(st0 + aRowBase + ((aCell0 + j * 16) ^ aXor)) =
                make_uint4(h[4*j], h[4*j+1], h[4*j+2], h[4*j+3]);
        const unsigned char* src = bG + (size_t)pc * 16384;
        uint32_t dst = sb + SM_STG(pc) + OFF_B;
        #pragma unroll
        for (int j = 0; j < 4; ++j)
            cp16(dst + tid * 16 + j * 4096, src + tid * 16 + j * 4096);
        CP_COMMIT;
    }
    CP_WAIT1;
    __syncthreads();

    for (int i = 0; i < NCHUNK; ++i) {
        // ---- fill stage (i+2)%3 with chunk i+2 ----
        if (i + 2 < NCHUNK) {
            const int s2 = (i + 2) % 3;
            const float4* ap = (const float4*)(aG + (i + 2) * BK);
            uint32_t h[16];
            #pragma unroll
            for (int j = 0; j < 8; ++j) {
                float4 v = ap[j];
                __half2 a = __float22half2_rn(make_float2(v.x, v.y));
                __half2 b = __float22half2_rn(make_float2(v.z, v.w));
                h[2*j]   = *(uint32_t*)&a;
                h[2*j+1] = *(uint32_t*)&b;
            }
            unsigned char* st2 = smem + SM_STG(s2);
            #pragma unroll
            for (int j = 0; j < 4; ++j)
                *(uint4*)(st2 + aRowBase + ((aCell0 + j * 16) ^ aXor)) =
                    make_uint4(h[4*j], h[4*j+1], h[4*j+2], h[4*j+3]);
            const unsigned char* src = bG + (size_t)(i + 2) * 16384;
            uint32_t dst = sb + SM_STG(s2) + OFF_B;
            #pragma unroll
            for (int j = 0; j < 4; ++j)
                cp16(dst + tid * 16 + j * 4096, src + tid * 16 + j * 4096);
            CP_COMMIT;
        }

        // ---- compute chunk i from stage i%3 ----
        const uint32_t stg = sb + SM_STG(i % 3);
        #pragma unroll
        for (int st = 0; st < 4; ++st) {
            const uint32_t sx = (uint32_t)(st << 5);
            uint32_t af[2][4];
            #pragma unroll
            for (int mt = 0; mt < 2; ++mt)
                ldsm4(af[mt], stg + aL_base + mt * 2048 +
                              (((sx + aL_cell) ^ ((aRowL & 7) << 4))));
            #pragma unroll
            for (int g = 0; g < 4; ++g) {
                uint32_t bf[4];
                ldsm4(bf, stg + OFF_B + bL_base + g * 2048 + ((sx + bL_cell) ^ bXor));
                #pragma unroll
                for (int half = 0; half < 2; ++half) {
                    const uint32_t* BH = &bf[half * 2];
                    #pragma unroll
                    for (int mt = 0; mt < 2; ++mt)
                        mma16816(acc[mt][2 * g + half], af[mt], BH);
                }
            }
        }

        if (i < NCHUNK - 2)       { CP_WAIT1; }
        else if (i == NCHUNK - 2) { CP_WAIT0; }
        if (i < NCHUNK - 1) __syncthreads();
    }

    // ---- epilogue: bias + squash (8-col group == one n8 tile) ----
    const int t4 = lane & 3, g8 = lane >> 2;
    #pragma unroll
    for (int mt = 0; mt < 2; ++mt) {
        const int row0 = b0 + wm * 32 + mt * 16 + g8;
        #pragma unroll
        for (int nt = 0; nt < 8; ++nt) {
            float* c = acc[mt][nt];
            const int cl = wn * 64 + nt * 8 + 2 * t4;
            const float bx = biasS[cl], by = biasS[cl + 1];
            float u0 = c[0] + bx, u1 = c[1] + by;
            float u2 = c[2] + bx, u3 = c[3] + by;
            float s0 = u0 * u0 + u1 * u1;
            float s1 = u2 * u2 + u3 * u3;
            s0 += __shfl_xor_sync(0xffffffffu, s0, 1);
            s0 += __shfl_xor_sync(0xffffffffu, s0, 2);
            s1 += __shfl_xor_sync(0xffffffffu, s1, 1);
            s1 += __shfl_xor_sync(0xffffffffu, s1, 2);
            float sc0 = s0 / ((1.0f + s0) * sqrtf(s0 + 1e-7f));
            float sc1 = s1 / ((1.0f + s1) * sqrtf(s1 + 1e-7f));
            float* p0 = out + (size_t)row0 * OUT_ROW + mod * 512 + n0 + cl;
            float* p1 = p0 + 8 * OUT_ROW;
            *(float2*)p0 = make_float2(u0 * sc0, u1 * sc0);
            *(float2*)p1 = make_float2(u2 * sc1, u3 * sc1);
        }
    }
}

extern "C" void kernel_launch(void* const* d_in, const int* in_sizes, int n_in,
                              void* d_out, int out_size)
{
    const float* x_img  = (const float*)d_in[0];
    const float* x_capt = (const float*)d_in[1];
    const float* x_dct  = (const float*)d_in[2];
    const float* w_img  = (const float*)d_in[3];
    const float* b_img  = (const float*)d_in[4];
    const float* w_capt = (const float*)d_in[5];
    const float* b_capt = (const float*)d_in[6];
    const float* w_dct  = (const float*)d_in[7];
    const float* b_dct  = (const float*)d_in[8];
    float* out = (float*)d_out;

    cudaFuncSetAttribute(caps_gemm, cudaFuncAttributeMaxDynamicSharedMemorySize, SMEM_TOTAL);

    caps_convw<<<576, 256>>>(w_img, w_capt, w_dct);

    dim3 grid(16384 / BM, 512 / BN, 3);   // (128, 4, 3)
    caps_gemm<<<grid, 256, SMEM_TOTAL>>>(x_img, x_capt, x_dct,
                                         b_img, b_capt, b_dct, out);
}

// round 9
// speedup vs baseline: 1.9887x; 1.4095x over previous
#include <cuda_runtime.h>
#include <cuda_fp16.h>
#include <cstdint>

#define IN_CH   768
#define OUT_ROW 1536
#define BM      128
#define BN      256
#define BK      64
#define NCHUNK  12          // 768/64

// smem: [0,1024) bias | 3 stages of 49152B: A 16K | B 32K
#define STGB     49152
#define SM_STG(s) (1024 + (s)*STGB)
#define OFF_B    16384
#define SMEM_TOTAL (1024 + 3*STGB)   // 148480 -> 1 CTA/SM

#define SWZ(o) ((o) ^ (((o) >> 3) & 0x70))

// Pre-converted fp16 activations, SW128-swizzled, layout == smem A block:
// [mod 3][mtile 128][kchunk 12][128 rows][128 B]
__device__ __align__(128) unsigned char g_Ascr[3*128*12*16384];   // 75.5 MB
// Pre-converted fp16 weights, layout == smem B block:
// [mod 3][ntile 2][kchunk 12][256 rows][128 B]
__device__ __align__(128) unsigned char g_Bscr[3*2*12*32768];

static __device__ __forceinline__ uint32_t s2u(const void* p) {
    uint32_t a;
    asm("{ .reg .u64 t; cvta.to.shared.u64 t, %1; cvt.u32.u64 %0, t; }" : "=r"(a) : "l"(p));
    return a;
}
static __device__ __forceinline__ void ldsm4(uint32_t* r, uint32_t addr) {
    asm volatile("ldmatrix.sync.aligned.m8n8.x4.shared.b16 {%0,%1,%2,%3}, [%4];"
                 : "=r"(r[0]), "=r"(r[1]), "=r"(r[2]), "=r"(r[3]) : "r"(addr));
}
static __device__ __forceinline__ void mma16816(float* c, const uint32_t* a, const uint32_t* b) {
    asm volatile("mma.sync.aligned.m16n8k16.row.col.f32.f16.f16.f32 "
                 "{%0,%1,%2,%3}, {%4,%5,%6,%7}, {%8,%9}, {%0,%1,%2,%3};"
                 : "+f"(c[0]), "+f"(c[1]), "+f"(c[2]), "+f"(c[3])
                 : "r"(a[0]), "r"(a[1]), "r"(a[2]), "r"(a[3]), "r"(b[0]), "r"(b[1]));
}
static __device__ __forceinline__ void cp16(uint32_t dst, const void* src) {
    asm volatile("cp.async.cg.shared.global [%0], [%1], 16;" :: "r"(dst), "l"(src) : "memory");
}
#define CP_COMMIT asm volatile("cp.async.commit_group;" ::: "memory")
#define CP_WAIT1  asm volatile("cp.async.wait_group 1;" ::: "memory")
#define CP_WAIT0  asm volatile("cp.async.wait_group 0;" ::: "memory")

// ============ kernel 0: activation conversion fp32 -> fp16 (swizzled) ============
__global__ __launch_bounds__(256)
void caps_convx(const float* __restrict__ x_img,
                const float* __restrict__ x_capt,
                const float* __restrict__ x_dct)
{
    int gt  = blockIdx.x * 256 + threadIdx.x;     // [0, 4718592)
    int mod = gt / 1572864;
    int r   = gt % 1572864;
    int b   = r / 96;                             // batch row [0,16384)
    int k8  = r % 96;                             // 8-float k group
    const float* X = (mod == 0) ? x_img : (mod == 1) ? x_capt : x_dct;
    const float4* src = (const float4*)(X + (size_t)b * IN_CH + k8 * 8);
    float4 p = src[0], q = src[1];
    __half2 h0 = __float22half2_rn(make_float2(p.x, p.y));
    __half2 h1 = __float22half2_rn(make_float2(p.z, p.w));
    __half2 h2 = __float22half2_rn(make_float2(q.x, q.y));
    __half2 h3 = __float22half2_rn(make_float2(q.z, q.w));
    int mtile = b >> 7, rloc = b & 127;
    int kch = k8 >> 3, cell = k8 & 7;
    uint32_t off = SWZ((uint32_t)(rloc * 128 + cell * 16));
    unsigned char* dst = g_Ascr + (size_t)(((mod * 128 + mtile) * 12) + kch) * 16384 + off;
    *(uint4*)dst = make_uint4(*(uint32_t*)&h0, *(uint32_t*)&h1, *(uint32_t*)&h2, *(uint32_t*)&h3);
}

// ============ kernel 1: weight conversion fp32 -> fp16 (swizzled) ============
__global__ __launch_bounds__(256)
void caps_convw(const float* __restrict__ w_img,
                const float* __restrict__ w_capt,
                const float* __restrict__ w_dct)
{
    int gt  = blockIdx.x * 256 + threadIdx.x;     // [0, 147456)
    int mod = gt / 49152;
    int r   = gt % 49152;
    int n   = r / 96;                             // output col within modality [0,512)
    int k8  = r % 96;
    const float* W = (mod == 0) ? w_img : (mod == 1) ? w_capt : w_dct;
    int wrow = ((n & 7) << 6) | (n >> 3);         // W row for col n = r*8 + c
    const float4* src = (const float4*)(W + (size_t)wrow * IN_CH + k8 * 8);
    float4 p = src[0], q = src[1];
    __half2 h0 = __float22half2_rn(make_float2(p.x, p.y));
    __half2 h1 = __float22half2_rn(make_float2(p.z, p.w));
    __half2 h2 = __float22half2_rn(make_float2(q.x, q.y));
    __half2 h3 = __float22half2_rn(make_float2(q.z, q.w));
    int ntile = n >> 8, rloc = n & 255;
    int kch = k8 >> 3, cell = k8 & 7;
    uint32_t off = SWZ((uint32_t)(rloc * 128 + cell * 16));
    unsigned char* dst = g_Bscr + (size_t)((mod * 2 + ntile) * 12 + kch) * 32768 + off;
    *(uint4*)dst = make_uint4(*(uint32_t*)&h0, *(uint32_t*)&h1, *(uint32_t*)&h2, *(uint32_t*)&h3);
}

// ============ kernel 2: fp16 mma.sync GEMM + bias + squash ============
// 8 warps, warp tile 64x64 (wm 2 x wn 4)
__global__ __launch_bounds__(256, 1)
void caps_gemm(const float* __restrict__ b_img,
               const float* __restrict__ b_capt,
               const float* __restrict__ b_dct,
               float* __restrict__ out)
{
    extern __shared__ __align__(1024) unsigned char smem[];
    const uint32_t sb = s2u(smem);
    float* biasS = (float*)smem;

    const int tid  = threadIdx.x;
    const int lane = tid & 31;
    const int w    = tid >> 5;
    const int wm   = w & 1;            // 2 warps over M (64 rows each)
    const int wn   = w >> 1;           // 4 warps over N (64 cols each)
    const int b0   = blockIdx.x * BM;
    const int n0   = blockIdx.y * BN;
    const int mod  = blockIdx.z;

    const float* Bv = (mod == 0) ? b_img : (mod == 1) ? b_capt : b_dct;
    { int n = n0 + tid; biasS[tid] = Bv[((n & 7) << 6) + (n >> 3)]; }

    // gmem sources (layouts identical to smem blocks)
    const unsigned char* aG = g_Ascr + (size_t)((mod * 128 + blockIdx.x) * 12) * 16384;
    const unsigned char* bG = g_Bscr + (size_t)((mod * 2 + blockIdx.y) * 12) * 32768;

    // ldsm consumer bases
    const uint32_t aXor  = (uint32_t)((lane & 7) << 4);
    const uint32_t aRowB = (uint32_t)((wm * 64 + (lane & 15)) * 128);
    const uint32_t aCell = (uint32_t)(((lane >> 4) & 1) * 16);
    const uint32_t bXor  = aXor;
    const uint32_t bRowB = (uint32_t)((wn * 64 + (lane & 7) + ((lane & 16) ? 8 : 0)) * 128);
    const uint32_t bCell = (uint32_t)((lane & 8) ? 16 : 0);

    float acc[4][8][4];
    #pragma unroll
    for (int i = 0; i < 4; ++i)
        #pragma unroll
        for (int j = 0; j < 8; ++j)
            #pragma unroll
            for (int k = 0; k < 4; ++k) acc[i][j][k] = 0.f;

    // ---- prologue: stages 0,1 <- chunks 0,1 ----
    #pragma unroll
    for (int pc = 0; pc < 2; ++pc) {
        uint32_t dst = sb + SM_STG(pc);
        const unsigned char* sa = aG + (size_t)pc * 16384;
        const unsigned char* sbp = bG + (size_t)pc * 32768;
        #pragma unroll
        for (int j = 0; j < 4; ++j)
            cp16(dst + tid * 16 + j * 4096, sa + tid * 16 + j * 4096);
        #pragma unroll
        for (int j = 0; j < 8; ++j)
            cp16(dst + OFF_B + tid * 16 + j * 4096, sbp + tid * 16 + j * 4096);
        CP_COMMIT;
    }
    CP_WAIT1;
    __syncthreads();

    for (int i = 0; i < NCHUNK; ++i) {
        // ---- fill stage (i+2)%3 with chunk i+2 ----
        if (i + 2 < NCHUNK) {
            uint32_t dst = sb + SM_STG((i + 2) % 3);
            const unsigned char* sa = aG + (size_t)(i + 2) * 16384;
            const unsigned char* sbp = bG + (size_t)(i + 2) * 32768;
            #pragma unroll
            for (int j = 0; j < 4; ++j)
                cp16(dst + tid * 16 + j * 4096, sa + tid * 16 + j * 4096);
            #pragma unroll
            for (int j = 0; j < 8; ++j)
                cp16(dst + OFF_B + tid * 16 + j * 4096, sbp + tid * 16 + j * 4096);
            CP_COMMIT;
        }

        // ---- compute chunk i from stage i%3 ----
        const uint32_t stg = sb + SM_STG(i % 3);
        #pragma unroll
        for (int st = 0; st < 4; ++st) {
            const uint32_t sx = (uint32_t)(st << 5);
            uint32_t af[4][4];
            #pragma unroll
            for (int mt = 0; mt < 4; ++mt)
                ldsm4(af[mt], stg + aRowB + mt * 2048 + ((sx + aCell) ^ aXor));
            #pragma unroll
            for (int g = 0; g < 4; ++g) {
                uint32_t bf[4];
                ldsm4(bf, stg + OFF_B + bRowB + g * 2048 + ((sx + bCell) ^ bXor));
                #pragma unroll
                for (int half = 0; half < 2; ++half) {
                    const uint32_t* BH = &bf[half * 2];
                    #pragma unroll
                    for (int mt = 0; mt < 4; ++mt)
                        mma16816(acc[mt][2 * g + half], af[mt], BH);
                }
            }
        }

        if (i < NCHUNK - 2)       { CP_WAIT1; }
        else if (i == NCHUNK - 2) { CP_WAIT0; }
        if (i < NCHUNK - 1) __syncthreads();
    }

    // ---- epilogue: bias + squash (8-col group == one n8 tile) ----
    const int t4 = lane & 3, g8 = lane >> 2;
    #pragma unroll
    for (int mt = 0; mt < 4; ++mt) {
        const int row0 = b0 + wm * 64 + mt * 16 + g8;
        #pragma unroll
        for (int nt = 0; nt < 8; ++nt) {
            float* c = acc[mt][nt];
            const int cl = wn * 64 + nt * 8 + 2 * t4;
            const float bx = biasS[cl], by = biasS[cl + 1];
            float u0 = c[0] + bx, u1 = c[1] + by;
            float u2 = c[2] + bx, u3 = c[3] + by;
            float s0 = u0 * u0 + u1 * u1;
            float s1 = u2 * u2 + u3 * u3;
            s0 += __shfl_xor_sync(0xffffffffu, s0, 1);
            s0 += __shfl_xor_sync(0xffffffffu, s0, 2);
            s1 += __shfl_xor_sync(0xffffffffu, s1, 1);
            s1 += __shfl_xor_sync(0xffffffffu, s1, 2);
            float sc0 = s0 / ((1.0f + s0) * sqrtf(s0 + 1e-7f));
            float sc1 = s1 / ((1.0f + s1) * sqrtf(s1 + 1e-7f));
            float* p0 = out + (size_t)row0 * OUT_ROW + mod * 512 + n0 + cl;
            float* p1 = p0 + 8 * OUT_ROW;
            *(float2*)p0 = make_float2(u0 * sc0, u1 * sc0);
            *(float2*)p1 = make_float2(u2 * sc1, u3 * sc1);
        }
    }
}

extern "C" void kernel_launch(void* const* d_in, const int* in_sizes, int n_in,
                              void* d_out, int out_size)
{
    const float* x_img  = (const float*)d_in[0];
    const float* x_capt = (const float*)d_in[1];
    const float* x_dct  = (const float*)d_in[2];
    const float* w_img  = (const float*)d_in[3];
    const float* b_img  = (const float*)d_in[4];
    const float* w_capt = (const float*)d_in[5];
    const float* b_capt = (const float*)d_in[6];
    const float* w_dct  = (const float*)d_in[7];
    const float* b_dct  = (const float*)d_in[8];
    float* out = (float*)d_out;

    cudaFuncSetAttribute(caps_gemm, cudaFuncAttributeMaxDynamicSharedMemorySize, SMEM_TOTAL);

    caps_convx<<<18432, 256>>>(x_img, x_capt, x_dct);
    caps_convw<<<576, 256>>>(w_img, w_capt, w_dct);

    dim3 grid(16384 / BM, 512 / BN, 3);   // (128, 2, 3)
    caps_gemm<<<grid, 256, SMEM_TOTAL>>>(b_img, b_capt, b_dct, out);
}

// round 10
// speedup vs baseline: 2.3163x; 1.1647x over previous
#include <cuda_runtime.h>
#include <cuda_fp16.h>
#include <cstdint>

#define IN_CH   768
#define OUT_ROW 1536
#define BM      128
#define BN      128
#define BK      64
#define NCHUNK  12          // 768/64

// smem: [0,1024) bias | 3 stages of 32768B: A 16K | B 16K
#define STGB     32768
#define SM_STG(s) (1024 + (s)*STGB)
#define OFF_B    16384
#define SMEM_TOTAL (1024 + 3*STGB)   // 99328 -> 2 CTAs/SM

#define SWZ(o) ((o) ^ (((o) >> 3) & 0x70))

// Pre-converted fp16 activations, SW128-swizzled, layout == smem A block:
// [mod 3][mtile 128][kchunk 12][128 rows][128 B]
__device__ __align__(128) unsigned char g_Ascr[3*128*12*16384];
// Pre-converted fp16 weights, layout == smem B block:
// [mod 3][ntile 4][kchunk 12][128 rows][128 B]
__device__ __align__(128) unsigned char g_Bscr[3*4*12*16384];

static __device__ __forceinline__ uint32_t s2u(const void* p) {
    uint32_t a;
    asm("{ .reg .u64 t; cvta.to.shared.u64 t, %1; cvt.u32.u64 %0, t; }" : "=r"(a) : "l"(p));
    return a;
}
static __device__ __forceinline__ void ldsm4(uint32_t* r, uint32_t addr) {
    asm volatile("ldmatrix.sync.aligned.m8n8.x4.shared.b16 {%0,%1,%2,%3}, [%4];"
                 : "=r"(r[0]), "=r"(r[1]), "=r"(r[2]), "=r"(r[3]) : "r"(addr));
}
static __device__ __forceinline__ void mma16816(float* c, const uint32_t* a, const uint32_t* b) {
    asm volatile("mma.sync.aligned.m16n8k16.row.col.f32.f16.f16.f32 "
                 "{%0,%1,%2,%3}, {%4,%5,%6,%7}, {%8,%9}, {%0,%1,%2,%3};"
                 : "+f"(c[0]), "+f"(c[1]), "+f"(c[2]), "+f"(c[3])
                 : "r"(a[0]), "r"(a[1]), "r"(a[2]), "r"(a[3]), "r"(b[0]), "r"(b[1]));
}
static __device__ __forceinline__ void cp16(uint32_t dst, const void* src) {
    asm volatile("cp.async.cg.shared.global [%0], [%1], 16;" :: "r"(dst), "l"(src) : "memory");
}
#define CP_COMMIT asm volatile("cp.async.commit_group;" ::: "memory")
#define CP_WAIT1  asm volatile("cp.async.wait_group 1;" ::: "memory")
#define CP_WAIT0  asm volatile("cp.async.wait_group 0;" ::: "memory")

// ============ kernel 0: activation conversion fp32 -> fp16 (swizzled) ============
__global__ __launch_bounds__(256)
void caps_convx(const float* __restrict__ x_img,
                const float* __restrict__ x_capt,
                const float* __restrict__ x_dct)
{
    int gt  = blockIdx.x * 256 + threadIdx.x;     // [0, 4718592)
    int mod = gt / 1572864;
    int r   = gt % 1572864;
    int b   = r / 96;                             // batch row [0,16384)
    int k8  = r % 96;                             // 8-float k group
    const float* X = (mod == 0) ? x_img : (mod == 1) ? x_capt : x_dct;
    const float4* src = (const float4*)(X + (size_t)b * IN_CH + k8 * 8);
    float4 p = src[0], q = src[1];
    __half2 h0 = __float22half2_rn(make_float2(p.x, p.y));
    __half2 h1 = __float22half2_rn(make_float2(p.z, p.w));
    __half2 h2 = __float22half2_rn(make_float2(q.x, q.y));
    __half2 h3 = __float22half2_rn(make_float2(q.z, q.w));
    int mtile = b >> 7, rloc = b & 127;
    int kch = k8 >> 3, cell = k8 & 7;
    uint32_t off = SWZ((uint32_t)(rloc * 128 + cell * 16));
    unsigned char* dst = g_Ascr + (size_t)(((mod * 128 + mtile) * 12) + kch) * 16384 + off;
    *(uint4*)dst = make_uint4(*(uint32_t*)&h0, *(uint32_t*)&h1, *(uint32_t*)&h2, *(uint32_t*)&h3);
}

// ============ kernel 1: weight conversion fp32 -> fp16 (swizzled) ============
__global__ __launch_bounds__(256)
void caps_convw(const float* __restrict__ w_img,
                const float* __restrict__ w_capt,
                const float* __restrict__ w_dct)
{
    int gt  = blockIdx.x * 256 + threadIdx.x;     // [0, 147456)
    int mod = gt / 49152;
    int r   = gt % 49152;
    int n   = r / 96;                             // output col within modality [0,512)
    int k8  = r % 96;
    const float* W = (mod == 0) ? w_img : (mod == 1) ? w_capt : w_dct;
    int wrow = ((n & 7) << 6) | (n >> 3);         // W row for col n = r*8 + c
    const float4* src = (const float4*)(W + (size_t)wrow * IN_CH + k8 * 8);
    float4 p = src[0], q = src[1];
    __half2 h0 = __float22half2_rn(make_float2(p.x, p.y));
    __half2 h1 = __float22half2_rn(make_float2(p.z, p.w));
    __half2 h2 = __float22half2_rn(make_float2(q.x, q.y));
    __half2 h3 = __float22half2_rn(make_float2(q.z, q.w));
    int ntile = n >> 7, rloc = n & 127;
    int kch = k8 >> 3, cell = k8 & 7;
    uint32_t off = SWZ((uint32_t)(rloc * 128 + cell * 16));
    unsigned char* dst = g_Bscr + (size_t)((mod * 4 + ntile) * 12 + kch) * 16384 + off;
    *(uint4*)dst = make_uint4(*(uint32_t*)&h0, *(uint32_t*)&h1, *(uint32_t*)&h2, *(uint32_t*)&h3);
}

// ============ kernel 2: fp16 mma.sync GEMM + bias + squash ============
// 4 warps, warp tile 64x64 (wm 2 x wn 2), 2 CTAs/SM
__global__ __launch_bounds__(128, 2)
void caps_gemm(const float* __restrict__ b_img,
               const float* __restrict__ b_capt,
               const float* __restrict__ b_dct,
               float* __restrict__ out)
{
    extern __shared__ __align__(1024) unsigned char smem[];
    const uint32_t sb = s2u(smem);
    float* biasS = (float*)smem;

    const int tid  = threadIdx.x;
    const int lane = tid & 31;
    const int w    = tid >> 5;
    const int wm   = w & 1;            // 2 warps over M (64 rows each)
    const int wn   = w >> 1;           // 2 warps over N (64 cols each)
    const int b0   = blockIdx.x * BM;
    const int n0   = blockIdx.y * BN;
    const int mod  = blockIdx.z;

    const float* Bv = (mod == 0) ? b_img : (mod == 1) ? b_capt : b_dct;
    { int n = n0 + tid; biasS[tid] = Bv[((n & 7) << 6) + (n >> 3)]; }

    // gmem sources (layouts identical to smem blocks)
    const unsigned char* aG = g_Ascr + (size_t)((mod * 128 + blockIdx.x) * 12) * 16384;
    const unsigned char* bG = g_Bscr + (size_t)((mod * 4 + blockIdx.y) * 12) * 16384;

    // ldsm consumer bases
    const uint32_t aXor  = (uint32_t)((lane & 7) << 4);
    const uint32_t aRowB = (uint32_t)((wm * 64 + (lane & 15)) * 128);
    const uint32_t aCell = (uint32_t)(((lane >> 4) & 1) * 16);
    const uint32_t bXor  = aXor;
    const uint32_t bRowB = (uint32_t)((wn * 64 + (lane & 7) + ((lane & 16) ? 8 : 0)) * 128);
    const uint32_t bCell = (uint32_t)((lane & 8) ? 16 : 0);

    float acc[4][8][4];
    #pragma unroll
    for (int i = 0; i < 4; ++i)
        #pragma unroll
        for (int j = 0; j < 8; ++j)
            #pragma unroll
            for (int k = 0; k < 4; ++k) acc[i][j][k] = 0.f;

    // ---- prologue: stages 0,1 <- chunks 0,1 (8+8 cp16 per thread) ----
    #pragma unroll
    for (int pc = 0; pc < 2; ++pc) {
        uint32_t dst = sb + SM_STG(pc);
        const unsigned char* sa = aG + (size_t)pc * 16384;
        const unsigned char* sbp = bG + (size_t)pc * 16384;
        #pragma unroll
        for (int j = 0; j < 8; ++j) {
            cp16(dst + tid * 16 + j * 2048,         sa + tid * 16 + j * 2048);
            cp16(dst + OFF_B + tid * 16 + j * 2048, sbp + tid * 16 + j * 2048);
        }
        CP_COMMIT;
    }
    CP_WAIT1;
    __syncthreads();

    for (int i = 0; i < NCHUNK; ++i) {
        // ---- fill stage (i+2)%3 with chunk i+2 ----
        if (i + 2 < NCHUNK) {
            uint32_t dst = sb + SM_STG((i + 2) % 3);
            const unsigned char* sa = aG + (size_t)(i + 2) * 16384;
            const unsigned char* sbp = bG + (size_t)(i + 2) * 16384;
            #pragma unroll
            for (int j = 0; j < 8; ++j) {
                cp16(dst + tid * 16 + j * 2048,         sa + tid * 16 + j * 2048);
                cp16(dst + OFF_B + tid * 16 + j * 2048, sbp + tid * 16 + j * 2048);
            }
            CP_COMMIT;
        }

        // ---- compute chunk i from stage i%3 ----
        const uint32_t stg = sb + SM_STG(i % 3);
        #pragma unroll
        for (int st = 0; st < 4; ++st) {
            const uint32_t sx = (uint32_t)(st << 5);
            uint32_t af[4][4];
            #pragma unroll
            for (int mt = 0; mt < 4; ++mt)
                ldsm4(af[mt], stg + aRowB + mt * 2048 + ((sx + aCell) ^ aXor));
            #pragma unroll
            for (int g = 0; g < 4; ++g) {
                uint32_t bf[4];
                ldsm4(bf, stg + OFF_B + bRowB + g * 2048 + ((sx + bCell) ^ bXor));
                #pragma unroll
                for (int half = 0; half < 2; ++half) {
                    const uint32_t* BH = &bf[half * 2];
                    #pragma unroll
                    for (int mt = 0; mt < 4; ++mt)
                        mma16816(acc[mt][2 * g + half], af[mt], BH);
                }
            }
        }

        if (i < NCHUNK - 2)       { CP_WAIT1; }
        else if (i == NCHUNK - 2) { CP_WAIT0; }
        if (i < NCHUNK - 1) __syncthreads();
    }

    // ---- epilogue: bias + squash (8-col group == one n8 tile) ----
    const int t4 = lane & 3, g8 = lane >> 2;
    #pragma unroll
    for (int mt = 0; mt < 4; ++mt) {
        const int row0 = b0 + wm * 64 + mt * 16 + g8;
        #pragma unroll
        for (int nt = 0; nt < 8; ++nt) {
            float* c = acc[mt][nt];
            const int cl = wn * 64 + nt * 8 + 2 * t4;
            const float bx = biasS[cl], by = biasS[cl + 1];
            float u0 = c[0] + bx, u1 = c[1] + by;
            float u2 = c[2] + bx, u3 = c[3] + by;
            float s0 = u0 * u0 + u1 * u1;
            float s1 = u2 * u2 + u3 * u3;
            s0 += __shfl_xor_sync(0xffffffffu, s0, 1);
            s0 += __shfl_xor_sync(0xffffffffu, s0, 2);
            s1 += __shfl_xor_sync(0xffffffffu, s1, 1);
            s1 += __shfl_xor_sync(0xffffffffu, s1, 2);
            float sc0 = s0 / ((1.0f + s0) * sqrtf(s0 + 1e-7f));
            float sc1 = s1 / ((1.0f + s1) * sqrtf(s1 + 1e-7f));
            float* p0 = out + (size_t)row0 * OUT_ROW + mod * 512 + n0 + cl;
            float* p1 = p0 + 8 * OUT_ROW;
            *(float2*)p0 = make_float2(u0 * sc0, u1 * sc0);
            *(float2*)p1 = make_float2(u2 * sc1, u3 * sc1);
        }
    }
}

extern "C" void kernel_launch(void* const* d_in, const int* in_sizes, int n_in,
                              void* d_out, int out_size)
{
    const float* x_img  = (const float*)d_in[0];
    const float* x_capt = (const float*)d_in[1];
    const float* x_dct  = (const float*)d_in[2];
    const float* w_img  = (const float*)d_in[3];
    const float* b_img  = (const float*)d_in[4];
    const float* w_capt = (const float*)d_in[5];
    const float* b_capt = (const float*)d_in[6];
    const float* w_dct  = (const float*)d_in[7];
    const float* b_dct  = (const float*)d_in[8];
    float* out = (float*)d_out;

    cudaFuncSetAttribute(caps_gemm, cudaFuncAttributeMaxDynamicSharedMemorySize, SMEM_TOTAL);

    caps_convx<<<18432, 256>>>(x_img, x_capt, x_dct);
    caps_convw<<<576, 256>>>(w_img, w_capt, w_dct);

    dim3 grid(16384 / BM, 512 / BN, 3);   // (128, 4, 3)
    caps_gemm<<<grid, 128, SMEM_TOTAL>>>(b_img, b_capt, b_dct, out);
}

// round 11
// speedup vs baseline: 2.3472x; 1.0134x over previous
#include <cuda_runtime.h>
#include <cuda_fp16.h>
#include <cstdint>

#define IN_CH   768
#define OUT_ROW 1536
#define BM      128
#define BN      128
#define BK      64
#define NCHUNK  12          // 768/64

// smem: [0,1024) bias | 3 stages of 32768B: A 16K | B 16K
#define STGB     32768
#define SM_STG(s) (1024 + (s)*STGB)
#define OFF_B    16384
#define SMEM_TOTAL (1024 + 3*STGB)   // 99328 -> 2 CTAs/SM

#define SWZ(o) ((o) ^ (((o) >> 3) & 0x70))

// Pre-converted fp16 activations, SW128-swizzled, layout == smem A block:
// [mod 3][mtile 128][kchunk 12][128 rows][128 B]
__device__ __align__(128) unsigned char g_Ascr[3*128*12*16384];
// Pre-converted fp16 weights, layout == smem B block:
// [mod 3][ntile 4][kchunk 12][128 rows][128 B]
__device__ __align__(128) unsigned char g_Bscr[3*4*12*16384];

static __device__ __forceinline__ uint32_t s2u(const void* p) {
    uint32_t a;
    asm("{ .reg .u64 t; cvta.to.shared.u64 t, %1; cvt.u32.u64 %0, t; }" : "=r"(a) : "l"(p));
    return a;
}
static __device__ __forceinline__ void ldsm4(uint32_t* r, uint32_t addr) {
    asm volatile("ldmatrix.sync.aligned.m8n8.x4.shared.b16 {%0,%1,%2,%3}, [%4];"
                 : "=r"(r[0]), "=r"(r[1]), "=r"(r[2]), "=r"(r[3]) : "r"(addr));
}
static __device__ __forceinline__ void mma16816(float* c, const uint32_t* a, const uint32_t* b) {
    asm volatile("mma.sync.aligned.m16n8k16.row.col.f32.f16.f16.f32 "
                 "{%0,%1,%2,%3}, {%4,%5,%6,%7}, {%8,%9}, {%0,%1,%2,%3};"
                 : "+f"(c[0]), "+f"(c[1]), "+f"(c[2]), "+f"(c[3])
                 : "r"(a[0]), "r"(a[1]), "r"(a[2]), "r"(a[3]), "r"(b[0]), "r"(b[1]));
}
static __device__ __forceinline__ void cp16(uint32_t dst, const void* src) {
    asm volatile("cp.async.cg.shared.global [%0], [%1], 16;" :: "r"(dst), "l"(src) : "memory");
}
#define CP_COMMIT asm volatile("cp.async.commit_group;" ::: "memory")
#define CP_WAIT1  asm volatile("cp.async.wait_group 1;" ::: "memory")
#define CP_WAIT0  asm volatile("cp.async.wait_group 0;" ::: "memory")

// ============ kernel 0: activation conversion fp32 -> fp16 (swizzled) ============
__global__ __launch_bounds__(256)
void caps_convx(const float* __restrict__ x_img,
                const float* __restrict__ x_capt,
                const float* __restrict__ x_dct)
{
    int gt  = blockIdx.x * 256 + threadIdx.x;     // [0, 4718592)
    int mod = gt / 1572864;
    int r   = gt % 1572864;
    int b   = r / 96;                             // batch row [0,16384)
    int k8  = r % 96;                             // 8-float k group
    const float* X = (mod == 0) ? x_img : (mod == 1) ? x_capt : x_dct;
    const float4* src = (const float4*)(X + (size_t)b * IN_CH + k8 * 8);
    float4 p = src[0], q = src[1];
    __half2 h0 = __float22half2_rn(make_float2(p.x, p.y));
    __half2 h1 = __float22half2_rn(make_float2(p.z, p.w));
    __half2 h2 = __float22half2_rn(make_float2(q.x, q.y));
    __half2 h3 = __float22half2_rn(make_float2(q.z, q.w));
    int mtile = b >> 7, rloc = b & 127;
    int kch = k8 >> 3, cell = k8 & 7;
    uint32_t off = SWZ((uint32_t)(rloc * 128 + cell * 16));
    unsigned char* dst = g_Ascr + (size_t)(((mod * 128 + mtile) * 12) + kch) * 16384 + off;
    *(uint4*)dst = make_uint4(*(uint32_t*)&h0, *(uint32_t*)&h1, *(uint32_t*)&h2, *(uint32_t*)&h3);
}

// ============ kernel 1: weight conversion fp32 -> fp16 (swizzled) ============
__global__ __launch_bounds__(256)
void caps_convw(const float* __restrict__ w_img,
                const float* __restrict__ w_capt,
                const float* __restrict__ w_dct)
{
    int gt  = blockIdx.x * 256 + threadIdx.x;     // [0, 147456)
    int mod = gt / 49152;
    int r   = gt % 49152;
    int n   = r / 96;                             // output col within modality [0,512)
    int k8  = r % 96;
    const float* W = (mod == 0) ? w_img : (mod == 1) ? w_capt : w_dct;
    int wrow = ((n & 7) << 6) | (n >> 3);         // W row for col n = r*8 + c
    const float4* src = (const float4*)(W + (size_t)wrow * IN_CH + k8 * 8);
    float4 p = src[0], q = src[1];
    __half2 h0 = __float22half2_rn(make_float2(p.x, p.y));
    __half2 h1 = __float22half2_rn(make_float2(p.z, p.w));
    __half2 h2 = __float22half2_rn(make_float2(q.x, q.y));
    __half2 h3 = __float22half2_rn(make_float2(q.z, q.w));
    int ntile = n >> 7, rloc = n & 127;
    int kch = k8 >> 3, cell = k8 & 7;
    uint32_t off = SWZ((uint32_t)(rloc * 128 + cell * 16));
    unsigned char* dst = g_Bscr + (size_t)((mod * 4 + ntile) * 12 + kch) * 16384 + off;
    *(uint4*)dst = make_uint4(*(uint32_t*)&h0, *(uint32_t*)&h1, *(uint32_t*)&h2, *(uint32_t*)&h3);
}

// ============ kernel 2: fp16 mma.sync GEMM + bias + squash ============
// 4 warps, warp tile 64x64 (wm 2 x wn 2), 2 CTAs/SM, frag double-buffer over k-steps
__global__ __launch_bounds__(128, 2)
void caps_gemm(const float* __restrict__ b_img,
               const float* __restrict__ b_capt,
               const float* __restrict__ b_dct,
               float* __restrict__ out)
{
    extern __shared__ __align__(1024) unsigned char smem[];
    const uint32_t sb = s2u(smem);
    float* biasS = (float*)smem;

    const int tid  = threadIdx.x;
    const int lane = tid & 31;
    const int w    = tid >> 5;
    const int wm   = w & 1;            // 2 warps over M (64 rows each)
    const int wn   = w >> 1;           // 2 warps over N (64 cols each)
    const int b0   = blockIdx.y * BM;  // mtile on y
    const int n0   = blockIdx.x * BN;  // ntile on x (4 adjacent CTAs share A slab)
    const int mod  = blockIdx.z;

    const float* Bv = (mod == 0) ? b_img : (mod == 1) ? b_capt : b_dct;
    { int n = n0 + tid; biasS[tid] = Bv[((n & 7) << 6) + (n >> 3)]; }

    // gmem sources (layouts identical to smem blocks)
    const unsigned char* aG = g_Ascr + (size_t)((mod * 128 + blockIdx.y) * 12) * 16384;
    const unsigned char* bG = g_Bscr + (size_t)((mod * 4 + blockIdx.x) * 12) * 16384;

    // ldsm consumer bases
    const uint32_t aXor  = (uint32_t)((lane & 7) << 4);
    const uint32_t aRowB = (uint32_t)((wm * 64 + (lane & 15)) * 128);
    const uint32_t aCell = (uint32_t)(((lane >> 4) & 1) * 16);
    const uint32_t bXor  = aXor;
    const uint32_t bRowB = (uint32_t)((wn * 64 + (lane & 7) + ((lane & 16) ? 8 : 0)) * 128);
    const uint32_t bCell = (uint32_t)((lane & 8) ? 16 : 0);

    float acc[4][8][4];
    #pragma unroll
    for (int i = 0; i < 4; ++i)
        #pragma unroll
        for (int j = 0; j < 8; ++j)
            #pragma unroll
            for (int k = 0; k < 4; ++k) acc[i][j][k] = 0.f;

    // ---- prologue: stages 0,1 <- chunks 0,1 (8+8 cp16 per thread) ----
    #pragma unroll
    for (int pc = 0; pc < 2; ++pc) {
        uint32_t dst = sb + SM_STG(pc);
        const unsigned char* sa = aG + (size_t)pc * 16384;
        const unsigned char* sbp = bG + (size_t)pc * 16384;
        #pragma unroll
        for (int j = 0; j < 8; ++j) {
            cp16(dst + tid * 16 + j * 2048,         sa + tid * 16 + j * 2048);
            cp16(dst + OFF_B + tid * 16 + j * 2048, sbp + tid * 16 + j * 2048);
        }
        CP_COMMIT;
    }
    CP_WAIT1;
    __syncthreads();

    uint32_t af[2][4][4], bf[2][4][4];     // [buf][tile][frag]

    for (int i = 0; i < NCHUNK; ++i) {
        // ---- fill stage (i+2)%3 with chunk i+2 ----
        if (i + 2 < NCHUNK) {
            uint32_t dst = sb + SM_STG((i + 2) % 3);
            const unsigned char* sa = aG + (size_t)(i + 2) * 16384;
            const unsigned char* sbp = bG + (size_t)(i + 2) * 16384;
            #pragma unroll
            for (int j = 0; j < 8; ++j) {
                cp16(dst + tid * 16 + j * 2048,         sa + tid * 16 + j * 2048);
                cp16(dst + OFF_B + tid * 16 + j * 2048, sbp + tid * 16 + j * 2048);
            }
            CP_COMMIT;
        }

        // ---- compute chunk i from stage i%3: k-step software pipeline ----
        const uint32_t stg = sb + SM_STG(i % 3);

        // preload st=0 frags
        #pragma unroll
        for (int mt = 0; mt < 4; ++mt)
            ldsm4(af[0][mt], stg + aRowB + mt * 2048 + (aCell ^ aXor));
        #pragma unroll
        for (int g = 0; g < 4; ++g)
            ldsm4(bf[0][g], stg + OFF_B + bRowB + g * 2048 + (bCell ^ bXor));

        #pragma unroll
        for (int st = 0; st < 4; ++st) {
            const int cur = st & 1, nxt = cur ^ 1;
            if (st < 3) {                        // issue next k-step's ldsm before MMAs
                const uint32_t sx = (uint32_t)((st + 1) << 5);
                #pragma unroll
                for (int mt = 0; mt < 4; ++mt)
                    ldsm4(af[nxt][mt], stg + aRowB + mt * 2048 + ((sx + aCell) ^ aXor));
                #pragma unroll
                for (int g = 0; g < 4; ++g)
                    ldsm4(bf[nxt][g], stg + OFF_B + bRowB + g * 2048 + ((sx + bCell) ^ bXor));
            }
            #pragma unroll
            for (int g = 0; g < 4; ++g)
                #pragma unroll
                for (int half = 0; half < 2; ++half) {
                    const uint32_t* BH = &bf[cur][g][half * 2];
                    #pragma unroll
                    for (int mt = 0; mt < 4; ++mt)
                        mma16816(acc[mt][2 * g + half], af[cur][mt], BH);
                }
        }

        if (i < NCHUNK - 2)       { CP_WAIT1; }
        else if (i == NCHUNK - 2) { CP_WAIT0; }
        if (i < NCHUNK - 1) __syncthreads();
    }

    // ---- epilogue: bias + squash (8-col group == one n8 tile) ----
    const int t4 = lane & 3, g8 = lane >> 2;
    #pragma unroll
    for (int mt = 0; mt < 4; ++mt) {
        const int row0 = b0 + wm * 64 + mt * 16 + g8;
        #pragma unroll
        for (int nt = 0; nt < 8; ++nt) {
            float* c = acc[mt][nt];
            const int cl = wn * 64 + nt * 8 + 2 * t4;
            const float bx = biasS[cl], by = biasS[cl + 1];
            float u0 = c[0] + bx, u1 = c[1] + by;
            float u2 = c[2] + bx, u3 = c[3] + by;
            float s0 = u0 * u0 + u1 * u1;
            float s1 = u2 * u2 + u3 * u3;
            s0 += __shfl_xor_sync(0xffffffffu, s0, 1);
            s0 += __shfl_xor_sync(0xffffffffu, s0, 2);
            s1 += __shfl_xor_sync(0xffffffffu, s1, 1);
            s1 += __shfl_xor_sync(0xffffffffu, s1, 2);
            float sc0 = s0 / ((1.0f + s0) * sqrtf(s0 + 1e-7f));
            float sc1 = s1 / ((1.0f + s1) * sqrtf(s1 + 1e-7f));
            float* p0 = out + (size_t)row0 * OUT_ROW + mod * 512 + n0 + cl;
            float* p1 = p0 + 8 * OUT_ROW;
            *(float2*)p0 = make_float2(u0 * sc0, u1 * sc0);
            *(float2*)p1 = make_float2(u2 * sc1, u3 * sc1);
        }
    }
}

extern "C" void kernel_launch(void* const* d_in, const int* in_sizes, int n_in,
                              void* d_out, int out_size)
{
    const float* x_img  = (const float*)d_in[0];
    const float* x_capt = (const float*)d_in[1];
    const float* x_dct  = (const float*)d_in[2];
    const float* w_img  = (const float*)d_in[3];
    const float* b_img  = (const float*)d_in[4];
    const float* w_capt = (const float*)d_in[5];
    const float* b_capt = (const float*)d_in[6];
    const float* w_dct  = (const float*)d_in[7];
    const float* b_dct  = (const float*)d_in[8];
    float* out = (float*)d_out;

    cudaFuncSetAttribute(caps_gemm, cudaFuncAttributeMaxDynamicSharedMemorySize, SMEM_TOTAL);

    caps_convx<<<18432, 256>>>(x_img, x_capt, x_dct);
    caps_convw<<<576, 256>>>(w_img, w_capt, w_dct);

    dim3 grid(512 / BN, 16384 / BM, 3);   // (4, 128, 3): x=ntile shares A slab in L2
    caps_gemm<<<grid, 128, SMEM_TOTAL>>>(b_img, b_capt, b_dct, out);
}

// round 12
// speedup vs baseline: 2.4884x; 1.0601x over previous
#include <cuda_runtime.h>
#include <cuda_fp16.h>
#include <cstdint>

#define IN_CH   768
#define OUT_ROW 1536
#define BM      128
#define BN      128
#define BK      64
#define NCHUNK  12          // 768/64

// smem: [0,1024) bias | 2 stages of 32768B: A 16K | B 16K
#define STGB     32768
#define SM_STG(s) (1024 + (s)*STGB)
#define OFF_B    16384
#define SMEM_TOTAL (1024 + 2*STGB)   // 66560 -> 3 CTAs/SM

#define SWZ(o) ((o) ^ (((o) >> 3) & 0x70))

// Pre-converted fp16 activations, SW128-swizzled, layout == smem A block:
// [mod 3][mtile 128][kchunk 12][128 rows][128 B]
__device__ __align__(128) unsigned char g_Ascr[3*128*12*16384];
// Pre-converted fp16 weights, layout == smem B block:
// [mod 3][ntile 4][kchunk 12][128 rows][128 B]
__device__ __align__(128) unsigned char g_Bscr[3*4*12*16384];

static __device__ __forceinline__ uint32_t s2u(const void* p) {
    uint32_t a;
    asm("{ .reg .u64 t; cvta.to.shared.u64 t, %1; cvt.u32.u64 %0, t; }" : "=r"(a) : "l"(p));
    return a;
}
static __device__ __forceinline__ void ldsm4(uint32_t* r, uint32_t addr) {
    asm volatile("ldmatrix.sync.aligned.m8n8.x4.shared.b16 {%0,%1,%2,%3}, [%4];"
                 : "=r"(r[0]), "=r"(r[1]), "=r"(r[2]), "=r"(r[3]) : "r"(addr));
}
static __device__ __forceinline__ void mma16816(float* c, const uint32_t* a, const uint32_t* b) {
    asm volatile("mma.sync.aligned.m16n8k16.row.col.f32.f16.f16.f32 "
                 "{%0,%1,%2,%3}, {%4,%5,%6,%7}, {%8,%9}, {%0,%1,%2,%3};"
                 : "+f"(c[0]), "+f"(c[1]), "+f"(c[2]), "+f"(c[3])
                 : "r"(a[0]), "r"(a[1]), "r"(a[2]), "r"(a[3]), "r"(b[0]), "r"(b[1]));
}
static __device__ __forceinline__ void cp16(uint32_t dst, const void* src) {
    asm volatile("cp.async.cg.shared.global [%0], [%1], 16;" :: "r"(dst), "l"(src) : "memory");
}
#define CP_COMMIT asm volatile("cp.async.commit_group;" ::: "memory")
#define CP_WAIT0  asm volatile("cp.async.wait_group 0;" ::: "memory")

// ============ kernel 0: activation conversion fp32 -> fp16 (swizzled) ============
__global__ __launch_bounds__(256)
void caps_convx(const float* __restrict__ x_img,
                const float* __restrict__ x_capt,
                const float* __restrict__ x_dct)
{
    int gt  = blockIdx.x * 256 + threadIdx.x;     // [0, 4718592)
    int mod = gt / 1572864;
    int r   = gt % 1572864;
    int b   = r / 96;                             // batch row [0,16384)
    int k8  = r % 96;                             // 8-float k group
    const float* X = (mod == 0) ? x_img : (mod == 1) ? x_capt : x_dct;
    const float4* src = (const float4*)(X + (size_t)b * IN_CH + k8 * 8);
    float4 p = src[0], q = src[1];
    __half2 h0 = __float22half2_rn(make_float2(p.x, p.y));
    __half2 h1 = __float22half2_rn(make_float2(p.z, p.w));
    __half2 h2 = __float22half2_rn(make_float2(q.x, q.y));
    __half2 h3 = __float22half2_rn(make_float2(q.z, q.w));
    int mtile = b >> 7, rloc = b & 127;
    int kch = k8 >> 3, cell = k8 & 7;
    uint32_t off = SWZ((uint32_t)(rloc * 128 + cell * 16));
    unsigned char* dst = g_Ascr + (size_t)(((mod * 128 + mtile) * 12) + kch) * 16384 + off;
    *(uint4*)dst = make_uint4(*(uint32_t*)&h0, *(uint32_t*)&h1, *(uint32_t*)&h2, *(uint32_t*)&h3);
}

// ============ kernel 1: weight conversion fp32 -> fp16 (swizzled) ============
__global__ __launch_bounds__(256)
void caps_convw(const float* __restrict__ w_img,
                const float* __restrict__ w_capt,
                const float* __restrict__ w_dct)
{
    int gt  = blockIdx.x * 256 + threadIdx.x;     // [0, 147456)
    int mod = gt / 49152;
    int r   = gt % 49152;
    int n   = r / 96;                             // output col within modality [0,512)
    int k8  = r % 96;
    const float* W = (mod == 0) ? w_img : (mod == 1) ? w_capt : w_dct;
    int wrow = ((n & 7) << 6) | (n >> 3);         // W row for col n = r*8 + c
    const float4* src = (const float4*)(W + (size_t)wrow * IN_CH + k8 * 8);
    float4 p = src[0], q = src[1];
    __half2 h0 = __float22half2_rn(make_float2(p.x, p.y));
    __half2 h1 = __float22half2_rn(make_float2(p.z, p.w));
    __half2 h2 = __float22half2_rn(make_float2(q.x, q.y));
    __half2 h3 = __float22half2_rn(make_float2(q.z, q.w));
    int ntile = n >> 7, rloc = n & 127;
    int kch = k8 >> 3, cell = k8 & 7;
    uint32_t off = SWZ((uint32_t)(rloc * 128 + cell * 16));
    unsigned char* dst = g_Bscr + (size_t)((mod * 4 + ntile) * 12 + kch) * 16384 + off;
    *(uint4*)dst = make_uint4(*(uint32_t*)&h0, *(uint32_t*)&h1, *(uint32_t*)&h2, *(uint32_t*)&h3);
}

// ============ kernel 2: fp16 mma.sync GEMM + bias + squash ============
// 4 warps, warp tile 64x64 (wm 2 x wn 2), 3 CTAs/SM, 2-stage pipeline
__global__ __launch_bounds__(128, 3)
void caps_gemm(const float* __restrict__ b_img,
               const float* __restrict__ b_capt,
               const float* __restrict__ b_dct,
               float* __restrict__ out)
{
    extern __shared__ __align__(1024) unsigned char smem[];
    const uint32_t sb = s2u(smem);
    float* biasS = (float*)smem;

    const int tid  = threadIdx.x;
    const int lane = tid & 31;
    const int w    = tid >> 5;
    const int wm   = w & 1;            // 2 warps over M (64 rows each)
    const int wn   = w >> 1;           // 2 warps over N (64 cols each)
    const int b0   = blockIdx.y * BM;  // mtile on y
    const int n0   = blockIdx.x * BN;  // ntile on x (4 adjacent CTAs share A slab)
    const int mod  = blockIdx.z;

    const float* Bv = (mod == 0) ? b_img : (mod == 1) ? b_capt : b_dct;
    { int n = n0 + tid; biasS[tid] = Bv[((n & 7) << 6) + (n >> 3)]; }

    // gmem sources (layouts identical to smem blocks)
    const unsigned char* aG = g_Ascr + (size_t)((mod * 128 + blockIdx.y) * 12) * 16384;
    const unsigned char* bG = g_Bscr + (size_t)((mod * 4 + blockIdx.x) * 12) * 16384;

    // ldsm consumer bases
    const uint32_t aXor  = (uint32_t)((lane & 7) << 4);
    const uint32_t aRowB = (uint32_t)((wm * 64 + (lane & 15)) * 128);
    const uint32_t aCell = (uint32_t)(((lane >> 4) & 1) * 16);
    const uint32_t bXor  = aXor;
    const uint32_t bRowB = (uint32_t)((wn * 64 + (lane & 7) + ((lane & 16) ? 8 : 0)) * 128);
    const uint32_t bCell = (uint32_t)((lane & 8) ? 16 : 0);

    float acc[4][8][4];
    #pragma unroll
    for (int i = 0; i < 4; ++i)
        #pragma unroll
        for (int j = 0; j < 8; ++j)
            #pragma unroll
            for (int k = 0; k < 4; ++k) acc[i][j][k] = 0.f;

    // ---- prologue: stage 0 <- chunk 0 ----
    {
        uint32_t dst = sb + SM_STG(0);
        #pragma unroll
        for (int j = 0; j < 8; ++j) {
            cp16(dst + tid * 16 + j * 2048,         aG + tid * 16 + j * 2048);
            cp16(dst + OFF_B + tid * 16 + j * 2048, bG + tid * 16 + j * 2048);
        }
        CP_COMMIT;
    }
    CP_WAIT0;
    __syncthreads();

    for (int i = 0; i < NCHUNK; ++i) {
        // ---- issue cp for chunk i+1 into the other stage ----
        if (i + 1 < NCHUNK) {
            uint32_t dst = sb + SM_STG((i + 1) & 1);
            const unsigned char* sa = aG + (size_t)(i + 1) * 16384;
            const unsigned char* sbp = bG + (size_t)(i + 1) * 16384;
            #pragma unroll
            for (int j = 0; j < 8; ++j) {
                cp16(dst + tid * 16 + j * 2048,         sa + tid * 16 + j * 2048);
                cp16(dst + OFF_B + tid * 16 + j * 2048, sbp + tid * 16 + j * 2048);
            }
            CP_COMMIT;
        }

        // ---- compute chunk i from stage i&1 ----
        const uint32_t stg = sb + SM_STG(i & 1);
        #pragma unroll
        for (int st = 0; st < 4; ++st) {
            const uint32_t sx = (uint32_t)(st << 5);
            uint32_t af[4][4];
            #pragma unroll
            for (int mt = 0; mt < 4; ++mt)
                ldsm4(af[mt], stg + aRowB + mt * 2048 + ((sx + aCell) ^ aXor));
            #pragma unroll
            for (int g = 0; g < 4; ++g) {
                uint32_t bf[4];
                ldsm4(bf, stg + OFF_B + bRowB + g * 2048 + ((sx + bCell) ^ bXor));
                #pragma unroll
                for (int half = 0; half < 2; ++half) {
                    const uint32_t* BH = &bf[half * 2];
                    #pragma unroll
                    for (int mt = 0; mt < 4; ++mt)
                        mma16816(acc[mt][2 * g + half], af[mt], BH);
                }
            }
        }

        if (i + 1 < NCHUNK) {
            CP_WAIT0;            // chunk i+1 landed
            __syncthreads();     // everyone done reading stage (i+1)&1's old data & cp visible
        }
    }

    // ---- epilogue: bias + squash (8-col group == one n8 tile) ----
    const int t4 = lane & 3, g8 = lane >> 2;
    #pragma unroll
    for (int mt = 0; mt < 4; ++mt) {
        const int row0 = b0 + wm * 64 + mt * 16 + g8;
        #pragma unroll
        for (int nt = 0; nt < 8; ++nt) {
            float* c = acc[mt][nt];
            const int cl = wn * 64 + nt * 8 + 2 * t4;
            const float bx = biasS[cl], by = biasS[cl + 1];
            float u0 = c[0] + bx, u1 = c[1] + by;
            float u2 = c[2] + bx, u3 = c[3] + by;
            float s0 = u0 * u0 + u1 * u1;
            float s1 = u2 * u2 + u3 * u3;
            s0 += __shfl_xor_sync(0xffffffffu, s0, 1);
            s0 += __shfl_xor_sync(0xffffffffu, s0, 2);
            s1 += __shfl_xor_sync(0xffffffffu, s1, 1);
            s1 += __shfl_xor_sync(0xffffffffu, s1, 2);
            float sc0 = s0 / ((1.0f + s0) * sqrtf(s0 + 1e-7f));
            float sc1 = s1 / ((1.0f + s1) * sqrtf(s1 + 1e-7f));
            float* p0 = out + (size_t)row0 * OUT_ROW + mod * 512 + n0 + cl;
            float* p1 = p0 + 8 * OUT_ROW;
            *(float2*)p0 = make_float2(u0 * sc0, u1 * sc0);
            *(float2*)p1 = make_float2(u2 * sc1, u3 * sc1);
        }
    }
}

extern "C" void kernel_launch(void* const* d_in, const int* in_sizes, int n_in,
                              void* d_out, int out_size)
{
    const float* x_img  = (const float*)d_in[0];
    const float* x_capt = (const float*)d_in[1];
    const float* x_dct  = (const float*)d_in[2];
    const float* w_img  = (const float*)d_in[3];
    const float* b_img  = (const float*)d_in[4];
    const float* w_capt = (const float*)d_in[5];
    const float* b_capt = (const float*)d_in[6];
    const float* w_dct  = (const float*)d_in[7];
    const float* b_dct  = (const float*)d_in[8];
    float* out = (float*)d_out;

    cudaFuncSetAttribute(caps_gemm, cudaFuncAttributeMaxDynamicSharedMemorySize, SMEM_TOTAL);

    caps_convx<<<18432, 256>>>(x_img, x_capt, x_dct);
    caps_convw<<<576, 256>>>(w_img, w_capt, w_dct);

    dim3 grid(512 / BN, 16384 / BM, 3);   // (4, 128, 3): x=ntile shares A slab in L2
    caps_gemm<<<grid, 128, SMEM_TOTAL>>>(b_img, b_capt, b_dct, out);
}